// round 1
// baseline (speedup 1.0000x reference)
#include <cuda_runtime.h>

#define NT   256
#define LROW 16384
#define N1   8199
#define N2   4107
#define N3   2061
#define N4   1038

// smem layout (floats)
#define OFF_A   0        // 8200  (a1, a3, rec1(2062), rec3(8200))
#define OFF_B   8200     // 4108  (a2, a4, rec2(4108))
#define OFF_D1  12308    // 8200
#define OFF_D2  20508    // 4108
#define OFF_D3  24616    // 2064
#define OFF_D4  26680    // 1040
#define SMEM_FLOATS 27720

__constant__ float c_H[16] = {
    0.05441584224308161f,    0.3128715909144659f,    0.6756307362980128f,
    0.5853546836548691f,    -0.015829105256023893f, -0.2840155429624281f,
    0.00047248457399797254f, 0.128747426620186f,    -0.01736930100202211f,
   -0.04408825393106472f,    0.013981027917015516f,  0.008746094047015655f,
   -0.00487035299301066f,   -0.0003917403729959771f, 0.0006754494059985568f,
   -0.00011747678400228192f
};

// ca[k] = sum_t H[t] * x[refl(2k+t-14)]
// cd[k] = sum_t (-1)^t H[15-t] * x[refl(2k+t-14)]
__device__ __forceinline__ void dwt_level(const float* __restrict__ xin, int n,
                                          float* __restrict__ ca,
                                          float* __restrict__ cd, int nout)
{
    for (int base = threadIdx.x * 4; base < nout; base += NT * 4) {
        float w[22];
        int m0 = 2 * base - 14;
        if (m0 >= 0 && m0 + 21 < n) {
            #pragma unroll
            for (int j = 0; j < 22; j++) w[j] = xin[m0 + j];
        } else {
            #pragma unroll
            for (int j = 0; j < 22; j++) {
                int m = m0 + j;
                m = (m < 0) ? (-1 - m) : m;
                m = (m >= n) ? (2 * n - 1 - m) : m;
                w[j] = xin[m];
            }
        }
        #pragma unroll
        for (int r = 0; r < 4; r++) {
            int k = base + r;
            if (k < nout) {
                float a = 0.f, d = 0.f;
                #pragma unroll
                for (int t = 0; t < 16; t++) {
                    float xv = w[2 * r + t];
                    a = fmaf(c_H[t], xv, a);
                    if (t & 1) d = fmaf(-c_H[15 - t], xv, d);
                    else       d = fmaf( c_H[15 - t], xv, d);
                }
                ca[k] = a;
                cd[k] = d;
            }
        }
    }
}

// rec[2p]   = sum_s H[14-2s]*ca[p+s] + H[2s+1]*cd[p+s]
// rec[2p+1] = sum_s H[15-2s]*ca[p+s] - H[2s]  *cd[p+s],  p in [0, n-8]
// (valid region never touches the zero padding -> no boundary logic)
template <bool VEC4>
__device__ __forceinline__ void idwt_level(const float* __restrict__ ca,
                                           const float* __restrict__ cd,
                                           int n, float* __restrict__ rec)
{
    int plim = n - 7;
    for (int p0 = threadIdx.x * 2; p0 < plim; p0 += NT * 2) {
        float a[9], d[9];
        #pragma unroll
        for (int j = 0; j < 9; j++) {
            int q = p0 + j;
            if (q > n - 1) q = n - 1;   // clamp (value unused when pair invalid)
            a[j] = ca[q];
            d[j] = cd[q];
        }
        float o0 = 0.f, o1 = 0.f, o2 = 0.f, o3 = 0.f;
        #pragma unroll
        for (int s = 0; s < 8; s++) {
            o0 = fmaf(c_H[14 - 2 * s], a[s],     o0);
            o0 = fmaf(c_H[2 * s + 1],  d[s],     o0);
            o1 = fmaf(c_H[15 - 2 * s], a[s],     o1);
            o1 = fmaf(-c_H[2 * s],     d[s],     o1);
            o2 = fmaf(c_H[14 - 2 * s], a[s + 1], o2);
            o2 = fmaf(c_H[2 * s + 1],  d[s + 1], o2);
            o3 = fmaf(c_H[15 - 2 * s], a[s + 1], o3);
            o3 = fmaf(-c_H[2 * s],     d[s + 1], o3);
        }
        if (VEC4) {
            *reinterpret_cast<float4*>(rec + 2 * p0) = make_float4(o0, o1, o2, o3);
        } else {
            rec[2 * p0]     = o0;
            rec[2 * p0 + 1] = o1;
            if (p0 + 1 < plim) {
                rec[2 * p0 + 2] = o2;
                rec[2 * p0 + 3] = o3;
            }
        }
    }
}

__global__ void __launch_bounds__(NT, 2)
wden_kernel(const float* __restrict__ x, float* __restrict__ out)
{
    extern __shared__ float sm[];
    float* A  = sm + OFF_A;
    float* B  = sm + OFF_B;
    float* D1 = sm + OFF_D1;
    float* D2 = sm + OFF_D2;
    float* D3 = sm + OFF_D3;
    float* D4 = sm + OFF_D4;

    __shared__ int      s_hist[256];
    __shared__ int      s_wsum[8];
    __shared__ int      s_woff[8];
    __shared__ unsigned s_pref;
    __shared__ int      s_rank;
    __shared__ float    s_thr;

    const int tid = threadIdx.x;
    const int row = blockIdx.x;
    const float* xin  = x   + (size_t)row * LROW;
    float*       orow = out + (size_t)row * LROW;

    // ---- analysis: 4 DWT levels ----
    dwt_level(xin, LROW, A, D1, N1);  __syncthreads();
    dwt_level(A,   N1,   B, D2, N2);  __syncthreads();
    dwt_level(B,   N2,   A, D3, N3);  __syncthreads();
    dwt_level(A,   N3,   B, D4, N4);  __syncthreads();

    // ---- exact median of |D1| via 4-round radix select on fp32 bits ----
    if (tid == 0) { s_pref = 0u; s_rank = (N1 - 1) / 2; }  // rank 4099
    __syncthreads();
    const int NPAD = ((N1 + NT - 1) / NT) * NT;
    for (int b = 3; b >= 0; --b) {
        s_hist[tid] = 0;
        __syncthreads();
        const unsigned pref = s_pref;
        const int rank = s_rank;
        const int sh = b * 8;
        for (int i = tid; i < NPAD; i += NT) {
            bool valid = (i < N1);
            unsigned u = valid ? __float_as_uint(fabsf(D1[i])) : 0u;
            bool mt = valid && ((b == 3) || ((u >> (sh + 8)) == pref));
            unsigned bin = (u >> sh) & 255u;
            unsigned key = mt ? bin : 256u;
            unsigned grp = __match_any_sync(0xffffffffu, key);
            int leader = __ffs(grp) - 1;
            if (mt && (tid & 31) == leader)
                atomicAdd(&s_hist[bin], __popc(grp));
        }
        __syncthreads();
        int v = s_hist[tid];
        int incl = v;
        #pragma unroll
        for (int o = 1; o < 32; o <<= 1) {
            int tsh = __shfl_up_sync(0xffffffffu, incl, o);
            if ((tid & 31) >= o) incl += tsh;
        }
        if ((tid & 31) == 31) s_wsum[tid >> 5] = incl;
        __syncthreads();
        if (tid == 0) {
            int acc = 0;
            #pragma unroll
            for (int wq = 0; wq < 8; wq++) { s_woff[wq] = acc; acc += s_wsum[wq]; }
        }
        __syncthreads();
        int excl = incl - v + s_woff[tid >> 5];
        if (rank >= excl && rank < excl + v) {   // exactly one winner bin
            s_pref = (pref << 8) | (unsigned)tid;
            s_rank = rank - excl;
        }
        __syncthreads();
    }
    if (tid == 0) {
        float med = __uint_as_float(s_pref);
        s_thr = (med / 0.6745f) * 4.4054649f;    // sqrt(2*ln(16384))
    }
    __syncthreads();
    const float thr = s_thr;

    // ---- soft threshold all detail bands in place ----
    for (int i = tid; i < N1; i += NT) { float v = D1[i]; float av = fabsf(v) - thr; D1[i] = av > 0.f ? copysignf(av, v) : 0.f; }
    for (int i = tid; i < N2; i += NT) { float v = D2[i]; float av = fabsf(v) - thr; D2[i] = av > 0.f ? copysignf(av, v) : 0.f; }
    for (int i = tid; i < N3; i += NT) { float v = D3[i]; float av = fabsf(v) - thr; D3[i] = av > 0.f ? copysignf(av, v) : 0.f; }
    for (int i = tid; i < N4; i += NT) { float v = D4[i]; float av = fabsf(v) - thr; D4[i] = av > 0.f ? copysignf(av, v) : 0.f; }
    __syncthreads();

    // ---- synthesis: 4 IDWT levels (last writes straight to GMEM) ----
    idwt_level<false>(B, D4, N4, A);   __syncthreads();  // A: 2062
    idwt_level<false>(A, D3, N3, B);   __syncthreads();  // B: 4108 (uses A[0..2060])
    idwt_level<false>(B, D2, N2, A);   __syncthreads();  // A: 8200 (uses B[0..4106])
    idwt_level<true >(A, D1, N1, orow);                  // 16384 (uses A[0..8198])
}

extern "C" void kernel_launch(void* const* d_in, const int* in_sizes, int n_in,
                              void* d_out, int out_size)
{
    const float* x = (const float*)d_in[0];
    float* out = (float*)d_out;
    int rows = in_sizes[0] / LROW;   // 128*16 = 2048

    const int smem_bytes = SMEM_FLOATS * sizeof(float);  // 110880
    cudaFuncSetAttribute(wden_kernel,
                         cudaFuncAttributeMaxDynamicSharedMemorySize, smem_bytes);
    wden_kernel<<<rows, NT, smem_bytes>>>(x, out);
}

// round 2
// speedup vs baseline: 1.1073x; 1.1073x over previous
#include <cuda_runtime.h>

#define NT   256
#define LROW 16384
#define N1   8199
#define N2   4107
#define N3   2061
#define N4   1038

// ---- skewed smem addressing: conflict-free for strides 1,2,4,8 ----
#define SK(i) ((i) + ((i) >> 5))

// skewed buffer sizes
#define A_SK    8456    // flat 8200
#define B_SK    4236    // flat 4108
#define OFF_A   0
#define OFF_B   8456
#define OFF_D1  12692   // flat 8200 -> 8456
#define OFF_D2  21148   // flat 4108 -> 4236
#define SMEM_FLOATS 25384

// D3/D4 live inside A's flat index space (dead regions at those times)
#define D3_FLAT 2560    // extent [2560, 4621) ; a3/rec4 use [0, 2062)
#define D4_FLAT 4640    // extent [4640, 5678)

// filter taps as compile-time literals (fold into FFMA immediates)
#define HLIT { \
    0.05441584224308161f,    0.3128715909144659f,    0.6756307362980128f, \
    0.5853546836548691f,    -0.015829105256023893f, -0.2840155429624281f, \
    0.00047248457399797254f, 0.128747426620186f,    -0.01736930100202211f, \
   -0.04408825393106472f,    0.013981027917015516f,  0.008746094047015655f, \
   -0.00487035299301066f,   -0.0003917403729959771f, 0.0006754494059985568f, \
   -0.00011747678400228192f }

// ---- DWT over skewed smem input ----
__device__ __forceinline__ void dwt_smem(const float* __restrict__ xin, int n,
                                         float* __restrict__ ca,
                                         float* __restrict__ cd, int nout)
{
    const float H[16] = HLIT;
    for (int base = threadIdx.x * 4; base < nout; base += NT * 4) {
        float w[22];
        int m0 = 2 * base - 14;
        if (m0 >= 0 && m0 + 21 < n) {
            #pragma unroll
            for (int j = 0; j < 22; j++) w[j] = xin[SK(m0 + j)];
        } else {
            #pragma unroll
            for (int j = 0; j < 22; j++) {
                int m = m0 + j;
                m = (m < 0) ? (-1 - m) : m;
                m = (m >= n) ? (2 * n - 1 - m) : m;
                w[j] = xin[SK(m)];
            }
        }
        #pragma unroll
        for (int r = 0; r < 4; r++) {
            int k = base + r;
            if (k < nout) {
                float a = 0.f, d = 0.f;
                #pragma unroll
                for (int t = 0; t < 16; t++) {
                    float xv = w[2 * r + t];
                    a = fmaf(H[t], xv, a);
                    d = fmaf((t & 1) ? -H[15 - t] : H[15 - t], xv, d);
                }
                ca[SK(k)] = a;
                cd[SK(k)] = d;
            }
        }
    }
}

// ---- level-1 DWT: global input via aligned float4 ----
__device__ __forceinline__ void dwt_global(const float* __restrict__ xg,
                                           float* __restrict__ ca,
                                           float* __restrict__ cd)
{
    const float H[16] = HLIT;
    for (int base = threadIdx.x * 4; base < N1; base += NT * 4) {
        float w[24];                 // flat [m0-2, m0+22)
        int m0 = 2 * base - 14;
        int lo = m0 - 2;             // = 8t-16: 16B aligned
        if (lo >= 0 && lo + 24 <= LROW) {
            const float4* p = reinterpret_cast<const float4*>(xg + lo);
            #pragma unroll
            for (int j = 0; j < 6; j++) {
                float4 v = p[j];
                w[4*j] = v.x; w[4*j+1] = v.y; w[4*j+2] = v.z; w[4*j+3] = v.w;
            }
        } else {
            #pragma unroll
            for (int j = 0; j < 24; j++) {
                int m = lo + j;
                m = (m < 0) ? (-1 - m) : m;
                m = (m >= LROW) ? (2 * LROW - 1 - m) : m;
                w[j] = xg[m];
            }
        }
        #pragma unroll
        for (int r = 0; r < 4; r++) {
            int k = base + r;
            if (k < N1) {
                float a = 0.f, d = 0.f;
                #pragma unroll
                for (int t = 0; t < 16; t++) {
                    float xv = w[2 * r + t + 2];
                    a = fmaf(H[t], xv, a);
                    d = fmaf((t & 1) ? -H[15 - t] : H[15 - t], xv, d);
                }
                ca[SK(k)] = a;
                cd[SK(k)] = d;
            }
        }
    }
}

// ---- IDWT, 4 output-pairs per thread ----
// rec[2p]   = sum_s H[14-2s]*ca[p+s] + H[2s+1]*cd[p+s]
// rec[2p+1] = sum_s H[15-2s]*ca[p+s] - H[2s]  *cd[p+s],  p in [0, n-8]
template <bool FINAL>
__device__ __forceinline__ void idwt(const float* __restrict__ ca,
                                     const float* __restrict__ cd,
                                     int n, float* __restrict__ rec)
{
    const float H[16] = HLIT;
    int plim = n - 7;
    for (int p0 = threadIdx.x * 4; p0 < plim; p0 += NT * 4) {
        float a[12], d[12];
        #pragma unroll
        for (int j = 0; j < 12; j++) {
            int q = p0 + j; if (q > n - 1) q = n - 1;   // clamp; unused if pair invalid
            a[j] = ca[SK(q)];
            d[j] = cd[SK(q)];
        }
        float o[8];
        #pragma unroll
        for (int pp = 0; pp < 4; pp++) {
            float e = 0.f, od = 0.f;
            #pragma unroll
            for (int s = 0; s < 8; s++) {
                e  = fmaf(H[14 - 2 * s], a[pp + s], e);
                e  = fmaf(H[2 * s + 1],  d[pp + s], e);
                od = fmaf(H[15 - 2 * s], a[pp + s], od);
                od = fmaf(-H[2 * s],     d[pp + s], od);
            }
            o[2 * pp] = e; o[2 * pp + 1] = od;
        }
        if (FINAL) {
            // n=N1: plim=8192, NT*4 | 8192 -> every iteration is full; 32B-aligned
            float4* pr = reinterpret_cast<float4*>(rec + 2 * p0);
            pr[0] = make_float4(o[0], o[1], o[2], o[3]);
            pr[1] = make_float4(o[4], o[5], o[6], o[7]);
        } else {
            #pragma unroll
            for (int pp = 0; pp < 4; pp++) {
                if (p0 + pp < plim) {
                    rec[SK(2 * (p0 + pp))]     = o[2 * pp];
                    rec[SK(2 * (p0 + pp) + 1)] = o[2 * pp + 1];
                }
            }
        }
    }
}

__global__ void __launch_bounds__(NT, 2)
wden_kernel(const float* __restrict__ x, float* __restrict__ out)
{
    extern __shared__ float sm[];
    float* A  = sm + OFF_A;
    float* B  = sm + OFF_B;
    float* D1 = sm + OFF_D1;
    float* D2 = sm + OFF_D2;
    float* D3 = A + D3_FLAT + (D3_FLAT >> 5);   // 32-aligned flat offset => SK identity holds
    float* D4 = A + D4_FLAT + (D4_FLAT >> 5);

    __shared__ int      s_hist[256];
    __shared__ int      s_wsum[8];
    __shared__ int      s_woff[8];
    __shared__ unsigned s_pref;
    __shared__ int      s_rank;
    __shared__ float    s_thr;

    const int tid = threadIdx.x;
    const int row = blockIdx.x;
    const float* xin  = x   + (size_t)row * LROW;
    float*       orow = out + (size_t)row * LROW;

    // ---- analysis: 4 DWT levels ----
    dwt_global(xin, A, D1);            __syncthreads();
    dwt_smem(A, N1, B, D2, N2);        __syncthreads();
    dwt_smem(B, N2, A, D3, N3);        __syncthreads();   // a3 -> A[0,2061), D3 in A-space
    dwt_smem(A, N3, B, D4, N4);        __syncthreads();   // a4 -> B, D4 in A-space

    // ---- exact median of |D1| via 4-round radix select on fp32 bits ----
    if (tid == 0) { s_pref = 0u; s_rank = (N1 - 1) / 2; }
    __syncthreads();
    const int NPAD = ((N1 + NT - 1) / NT) * NT;
    for (int b = 3; b >= 0; --b) {
        s_hist[tid] = 0;
        __syncthreads();
        const unsigned pref = s_pref;
        const int rank = s_rank;
        const int sh = b * 8;
        for (int i = tid; i < NPAD; i += NT) {
            bool valid = (i < N1);
            unsigned u = valid ? __float_as_uint(fabsf(D1[SK(i)])) : 0u;
            bool mt = valid && ((b == 3) || ((u >> (sh + 8)) == pref));
            unsigned bin = (u >> sh) & 255u;
            unsigned key = mt ? bin : 256u;
            unsigned grp = __match_any_sync(0xffffffffu, key);
            int leader = __ffs(grp) - 1;
            if (mt && (tid & 31) == leader)
                atomicAdd(&s_hist[bin], __popc(grp));
        }
        __syncthreads();
        int v = s_hist[tid];
        int incl = v;
        #pragma unroll
        for (int o = 1; o < 32; o <<= 1) {
            int tsh = __shfl_up_sync(0xffffffffu, incl, o);
            if ((tid & 31) >= o) incl += tsh;
        }
        if ((tid & 31) == 31) s_wsum[tid >> 5] = incl;
        __syncthreads();
        if (tid == 0) {
            int acc = 0;
            #pragma unroll
            for (int wq = 0; wq < 8; wq++) { s_woff[wq] = acc; acc += s_wsum[wq]; }
        }
        __syncthreads();
        int excl = incl - v + s_woff[tid >> 5];
        if (rank >= excl && rank < excl + v) {
            s_pref = (pref << 8) | (unsigned)tid;
            s_rank = rank - excl;
        }
        __syncthreads();
    }
    if (tid == 0) {
        float med = __uint_as_float(s_pref);
        s_thr = (med / 0.6745f) * 4.4054649f;   // sqrt(2*ln(16384))
    }
    __syncthreads();
    const float thr = s_thr;

    // ---- soft threshold all detail bands in place ----
    for (int i = tid; i < N1; i += NT) { float v = D1[SK(i)]; float av = fabsf(v) - thr; D1[SK(i)] = av > 0.f ? copysignf(av, v) : 0.f; }
    for (int i = tid; i < N2; i += NT) { float v = D2[SK(i)]; float av = fabsf(v) - thr; D2[SK(i)] = av > 0.f ? copysignf(av, v) : 0.f; }
    for (int i = tid; i < N3; i += NT) { float v = D3[SK(i)]; float av = fabsf(v) - thr; D3[SK(i)] = av > 0.f ? copysignf(av, v) : 0.f; }
    for (int i = tid; i < N4; i += NT) { float v = D4[SK(i)]; float av = fabsf(v) - thr; D4[SK(i)] = av > 0.f ? copysignf(av, v) : 0.f; }
    __syncthreads();

    // ---- synthesis: 4 IDWT levels (last writes straight to GMEM) ----
    idwt<false>(B, D4, N4, A);   __syncthreads();  // rec4: A flat[0,2062)
    idwt<false>(A, D3, N3, B);   __syncthreads();  // rec3: B flat[0,4108)
    idwt<false>(B, D2, N2, A);   __syncthreads();  // rec2: A flat[0,8200) (D3/D4 dead)
    idwt<true >(A, D1, N1, orow);                  // 16384 floats to GMEM
}

extern "C" void kernel_launch(void* const* d_in, const int* in_sizes, int n_in,
                              void* d_out, int out_size)
{
    const float* x = (const float*)d_in[0];
    float* out = (float*)d_out;
    int rows = in_sizes[0] / LROW;   // 2048

    const int smem_bytes = SMEM_FLOATS * sizeof(float);  // 101,536
    cudaFuncSetAttribute(wden_kernel,
                         cudaFuncAttributeMaxDynamicSharedMemorySize, smem_bytes);
    wden_kernel<<<rows, NT, smem_bytes>>>(x, out);
}

// round 3
// speedup vs baseline: 1.1776x; 1.0635x over previous
#include <cuda_runtime.h>

#define NT   256
#define LROW 16384
#define N1   8199
#define N2   4107
#define N3   2061
#define N4   1038

// skewed smem addressing: conflict-free for strides 1,2,4,8,32
#define SK(i) ((i) + ((i) >> 5))

#define A_SK    8456    // flat 8200
#define B_SK    4236    // flat 4108
#define OFF_A   0
#define OFF_B   8456
#define OFF_D2  12692   // flat 4108
#define SMEM_FLOATS 16928   // 67,712 bytes -> 3 blocks/SM

// D3/D4 overlay dead regions of A's flat space (32-aligned so SK composes)
#define D3_FLAT 2560    // extent [2560, 4621)
#define D4_FLAT 4640    // extent [4640, 5678)

#define HLIT { \
    0.05441584224308161f,    0.3128715909144659f,    0.6756307362980128f, \
    0.5853546836548691f,    -0.015829105256023893f, -0.2840155429624281f, \
    0.00047248457399797254f, 0.128747426620186f,    -0.01736930100202211f, \
   -0.04408825393106472f,    0.013981027917015516f,  0.008746094047015655f, \
   -0.00487035299301066f,   -0.0003917403729959771f, 0.0006754494059985568f, \
   -0.00011747678400228192f }

__device__ __forceinline__ float softthr(float v, float thr) {
    float av = fabsf(v) - thr;
    return av > 0.f ? copysignf(av, v) : 0.f;
}

// ---- internal DWT over skewed smem (4 outputs/thread, strided) ----
__device__ __forceinline__ void dwt_smem(const float* __restrict__ xin, int n,
                                         float* __restrict__ ca,
                                         float* __restrict__ cd, int nout)
{
    const float H[16] = HLIT;
    for (int base = threadIdx.x * 4; base < nout; base += NT * 4) {
        float w[22];
        int m0 = 2 * base - 14;
        if (m0 >= 0 && m0 + 21 < n) {
            #pragma unroll
            for (int j = 0; j < 22; j++) w[j] = xin[SK(m0 + j)];
        } else {
            #pragma unroll
            for (int j = 0; j < 22; j++) {
                int m = m0 + j;
                m = (m < 0) ? (-1 - m) : m;
                m = (m >= n) ? (2 * n - 1 - m) : m;
                w[j] = xin[SK(m)];
            }
        }
        #pragma unroll
        for (int r = 0; r < 4; r++) {
            int k = base + r;
            if (k < nout) {
                float a = 0.f, d = 0.f;
                #pragma unroll
                for (int t = 0; t < 16; t++) {
                    float xv = w[2 * r + t];
                    a = fmaf(H[t], xv, a);
                    d = fmaf((t & 1) ? -H[15 - t] : H[15 - t], xv, d);
                }
                ca[SK(k)] = a;
                cd[SK(k)] = d;
            }
        }
    }
}

// ---- internal IDWT (2 output-pairs/thread) with fused soft threshold on d ----
// rec[2p]   = sum_s H[14-2s]*ca[p+s] + H[2s+1]*cd[p+s]
// rec[2p+1] = sum_s H[15-2s]*ca[p+s] - H[2s]  *cd[p+s],  p in [0, n-8]
__device__ __forceinline__ void idwt2(const float* __restrict__ ca,
                                      const float* __restrict__ cd,
                                      int n, float* __restrict__ rec, float thr)
{
    const float H[16] = HLIT;
    int plim = n - 7;
    for (int p0 = threadIdx.x * 2; p0 < plim; p0 += NT * 2) {
        float a[9], d[9];
        #pragma unroll
        for (int j = 0; j < 9; j++) {
            int q = p0 + j; if (q > n - 1) q = n - 1;
            a[j] = ca[SK(q)];
            d[j] = softthr(cd[SK(q)], thr);
        }
        float o0 = 0.f, o1 = 0.f, o2 = 0.f, o3 = 0.f;
        #pragma unroll
        for (int s = 0; s < 8; s++) {
            o0 = fmaf(H[14 - 2 * s], a[s],     o0);
            o0 = fmaf(H[2 * s + 1],  d[s],     o0);
            o1 = fmaf(H[15 - 2 * s], a[s],     o1);
            o1 = fmaf(-H[2 * s],     d[s],     o1);
            o2 = fmaf(H[14 - 2 * s], a[s + 1], o2);
            o2 = fmaf(H[2 * s + 1],  d[s + 1], o2);
            o3 = fmaf(H[15 - 2 * s], a[s + 1], o3);
            o3 = fmaf(-H[2 * s],     d[s + 1], o3);
        }
        rec[SK(2 * p0)]     = o0;
        rec[SK(2 * p0 + 1)] = o1;
        if (p0 + 1 < plim) {
            rec[SK(2 * p0 + 2)] = o2;
            rec[SK(2 * p0 + 3)] = o3;
        }
    }
}

__global__ void __launch_bounds__(NT, 3)
wden_kernel(const float* __restrict__ x, float* __restrict__ out)
{
    extern __shared__ float sm[];
    float* A  = sm + OFF_A;
    float* B  = sm + OFF_B;
    float* D2 = sm + OFF_D2;
    float* D3 = A + D3_FLAT + (D3_FLAT >> 5);
    float* D4 = A + D4_FLAT + (D4_FLAT >> 5);

    __shared__ int      s_hist[256];
    __shared__ int      s_wsum[8];
    __shared__ int      s_woff[8];
    __shared__ unsigned s_pref;
    __shared__ int      s_rank;
    __shared__ float    s_thr;
    __shared__ float    s_d1tail[8];     // D1[8192..8198]
    __shared__ float    s_halo[8][8];    // per-warp lane-0's d1r[0..6]

    const int tid  = threadIdx.x;
    const int lane = tid & 31;
    const int warp = tid >> 5;
    const int row  = blockIdx.x;
    const float* xin  = x   + (size_t)row * LROW;
    float*       orow = out + (size_t)row * LROW;

    // ================= level-1 DWT: a1 -> smem A, d1 -> registers =================
    float d1r[32];
    {
        const float H[16] = HLIT;
        #pragma unroll
        for (int c = 0; c < 8; c++) {
            float w[24];                       // flat x[lo .. lo+24)
            int lo = 64 * tid + 8 * c - 16;    // 16B aligned; lo+24 <= 16384 always
            if (lo >= 0) {
                const float4* p = reinterpret_cast<const float4*>(xin + lo);
                #pragma unroll
                for (int j = 0; j < 6; j++) {
                    float4 v = p[j];
                    w[4*j] = v.x; w[4*j+1] = v.y; w[4*j+2] = v.z; w[4*j+3] = v.w;
                }
            } else {                           // only tid==0, c<2
                #pragma unroll
                for (int j = 0; j < 24; j++) {
                    int m = lo + j;
                    m = (m < 0) ? (-1 - m) : m;
                    w[j] = xin[m];
                }
            }
            #pragma unroll
            for (int r = 0; r < 4; r++) {
                int k = 32 * tid + 4 * c + r;  // always < 8192
                float a = 0.f, d = 0.f;
                #pragma unroll
                for (int t = 0; t < 16; t++) {
                    float xv = w[2 * r + t + 2];
                    a = fmaf(H[t], xv, a);
                    d = fmaf((t & 1) ? -H[15 - t] : H[15 - t], xv, d);
                }
                A[SK(k)] = a;
                d1r[4 * c + r] = d;
            }
        }
        if (tid == NT - 1) {                   // tail outputs k = 8192..8198
            for (int e = 0; e < 7; e++) {
                int k = 8192 + e;
                float a = 0.f, d = 0.f;
                #pragma unroll
                for (int t = 0; t < 16; t++) {
                    int m = 2 * k + t - 14;
                    if (m >= LROW) m = 2 * LROW - 1 - m;
                    float xv = xin[m];
                    a = fmaf(H[t], xv, a);
                    d = fmaf((t & 1) ? -H[15 - t] : H[15 - t], xv, d);
                }
                A[SK(k)] = a;
                s_d1tail[e] = d;
            }
        }
    }
    __syncthreads();

    // ================= levels 2..4 DWT in smem =================
    dwt_smem(A, N1, B, D2, N2);   __syncthreads();
    dwt_smem(B, N2, A, D3, N3);   __syncthreads();   // a3 -> A[0,2061)
    dwt_smem(A, N3, B, D4, N4);   __syncthreads();   // a4 -> B[0,1038)

    // ================= exact median of |d1| via radix select over registers =========
    if (tid == 0) { s_pref = 0u; s_rank = (N1 - 1) / 2; }
    __syncthreads();
    for (int b = 3; b >= 0; --b) {
        s_hist[tid] = 0;
        __syncthreads();
        const unsigned pref = s_pref;
        const int rank = s_rank;
        const int sh = b * 8;
        #pragma unroll
        for (int j = 0; j < 32; j++) {
            unsigned u = __float_as_uint(fabsf(d1r[j]));
            bool mt = (b == 3) || ((u >> (sh + 8)) == pref);
            unsigned bin = (u >> sh) & 255u;
            unsigned key = mt ? bin : 256u;
            unsigned grp = __match_any_sync(0xffffffffu, key);
            int leader = __ffs(grp) - 1;
            if (mt && lane == leader)
                atomicAdd(&s_hist[bin], __popc(grp));
        }
        if (tid == 0) {                      // 7-element tail
            for (int e = 0; e < 7; e++) {
                unsigned u = __float_as_uint(fabsf(s_d1tail[e]));
                bool mt = (b == 3) || ((u >> (sh + 8)) == pref);
                if (mt) atomicAdd(&s_hist[(u >> sh) & 255u], 1);
            }
        }
        __syncthreads();
        int v = s_hist[tid];
        int incl = v;
        #pragma unroll
        for (int o = 1; o < 32; o <<= 1) {
            int tsh = __shfl_up_sync(0xffffffffu, incl, o);
            if (lane >= o) incl += tsh;
        }
        if (lane == 31) s_wsum[warp] = incl;
        __syncthreads();
        if (tid == 0) {
            int acc = 0;
            #pragma unroll
            for (int wq = 0; wq < 8; wq++) { s_woff[wq] = acc; acc += s_wsum[wq]; }
        }
        __syncthreads();
        int excl = incl - v + s_woff[warp];
        if (rank >= excl && rank < excl + v) {
            s_pref = (pref << 8) | (unsigned)tid;
            s_rank = rank - excl;
        }
        __syncthreads();
    }
    if (tid == 0) {
        float med = __uint_as_float(s_pref);
        s_thr = (med / 0.6745f) * 4.4054649f;   // * sqrt(2*ln(16384))
    }
    __syncthreads();
    const float thr = s_thr;

    // ---- threshold d1 registers; stage halo + tail ----
    #pragma unroll
    for (int j = 0; j < 32; j++) d1r[j] = softthr(d1r[j], thr);
    if (lane == 0) {
        #pragma unroll
        for (int j = 0; j < 7; j++) s_halo[warp][j] = d1r[j];
    }
    if (tid == 0) {
        for (int e = 0; e < 7; e++) s_d1tail[e] = softthr(s_d1tail[e], thr);
    }

    // ================= synthesis =================
    idwt2(B, D4, N4, A, thr);   __syncthreads();   // rec4 -> A[0,2062)
    idwt2(A, D3, N3, B, thr);   __syncthreads();   // rec3 -> B[0,4108)
    idwt2(B, D2, N2, A, thr);   __syncthreads();   // rec2 -> A[0,8200)

    // ---- final IDWT: 32 output pairs per thread, d1 from registers ----
    {
        const float H[16] = HLIT;
        float nxt[7];
        #pragma unroll
        for (int j = 0; j < 7; j++)
            nxt[j] = __shfl_down_sync(0xffffffffu, d1r[j], 1);
        if (lane == 31) {
            #pragma unroll
            for (int j = 0; j < 7; j++)
                nxt[j] = (warp < 7) ? s_halo[warp + 1][j] : s_d1tail[j];
        }
        #pragma unroll
        for (int c = 0; c < 4; c++) {
            float aa[15];
            #pragma unroll
            for (int j = 0; j < 15; j++)
                aa[j] = A[SK(32 * tid + 8 * c + j)];
            #pragma unroll
            for (int h = 0; h < 4; h++) {          // 2 pairs per float4 store
                float4 o4;
                #pragma unroll
                for (int q = 0; q < 2; q++) {
                    int pp = 2 * h + q;
                    float e = 0.f, od = 0.f;
                    #pragma unroll
                    for (int s = 0; s < 8; s++) {
                        int di = 8 * c + pp + s;
                        float dv = (di < 32) ? d1r[di] : nxt[di - 32];
                        float av = aa[pp + s];
                        e  = fmaf(H[14 - 2 * s], av, e);
                        e  = fmaf(H[2 * s + 1],  dv, e);
                        od = fmaf(H[15 - 2 * s], av, od);
                        od = fmaf(-H[2 * s],     dv, od);
                    }
                    if (q == 0) { o4.x = e; o4.y = od; }
                    else        { o4.z = e; o4.w = od; }
                }
                *reinterpret_cast<float4*>(orow + 64 * tid + 16 * c + 4 * h) = o4;
            }
        }
    }
}

extern "C" void kernel_launch(void* const* d_in, const int* in_sizes, int n_in,
                              void* d_out, int out_size)
{
    const float* x = (const float*)d_in[0];
    float* out = (float*)d_out;
    int rows = in_sizes[0] / LROW;   // 2048

    const int smem_bytes = SMEM_FLOATS * sizeof(float);  // 67,712
    cudaFuncSetAttribute(wden_kernel,
                         cudaFuncAttributeMaxDynamicSharedMemorySize, smem_bytes);
    wden_kernel<<<rows, NT, smem_bytes>>>(x, out);
}

// round 4
// speedup vs baseline: 1.2013x; 1.0202x over previous
#include <cuda_runtime.h>

#define LROW 16384
#define N1 8199
#define N2 4107
#define N3 2061
#define N4 1038
#define ROWS_MAX 2048

// padded row strides (multiples of 4 -> float4-aligned rows)
#define S1 8200
#define S2 4108
#define S3 2064
#define S4 1040

// scratch: a-buffers are reused for rec-buffers (lifetimes disjoint)
__device__ float g_a1[(size_t)ROWS_MAX * S1];   // a1, later rec2
__device__ float g_d1[(size_t)ROWS_MAX * S1];
__device__ float g_a2[(size_t)ROWS_MAX * S2];   // a2, later rec3
__device__ float g_d2[(size_t)ROWS_MAX * S2];
__device__ float g_a3[(size_t)ROWS_MAX * S3];   // a3, later rec4
__device__ float g_d3[(size_t)ROWS_MAX * S3];
__device__ float g_a4[(size_t)ROWS_MAX * S4];
__device__ float g_d4[(size_t)ROWS_MAX * S4];
__device__ float g_thr[ROWS_MAX];

#define HLIT { \
    0.05441584224308161f,    0.3128715909144659f,    0.6756307362980128f, \
    0.5853546836548691f,    -0.015829105256023893f, -0.2840155429624281f, \
    0.00047248457399797254f, 0.128747426620186f,    -0.01736930100202211f, \
   -0.04408825393106472f,    0.013981027917015516f,  0.008746094047015655f, \
   -0.00487035299301066f,   -0.0003917403729959771f, 0.0006754494059985568f, \
   -0.00011747678400228192f }

__device__ __forceinline__ float softthr(float v, float thr) {
    float av = fabsf(v) - thr;
    return av > 0.f ? copysignf(av, v) : 0.f;
}

// ===================== K1: level-1 DWT + exact median -> thr =====================
// block per row; thread t computes positions 1024c + 4t + r (c<8, r<4);
// d1 kept in regs for the median radix-select; a1/d1 streamed to global raw.
__global__ void __launch_bounds__(256)
k_dwt1_med(const float* __restrict__ x, float* __restrict__ a1,
           float* __restrict__ d1, float* __restrict__ thr_out)
{
    __shared__ int      s_hist[256];
    __shared__ int      s_wsum[8];
    __shared__ int      s_woff[8];
    __shared__ unsigned s_pref;
    __shared__ int      s_rank;
    __shared__ float    s_tail[8];

    const float H[16] = HLIT;
    const int tid = threadIdx.x, lane = tid & 31, warp = tid >> 5;
    const float* xin = x  + (size_t)blockIdx.x * LROW;
    float* pa = a1 + (size_t)blockIdx.x * S1;
    float* pd = d1 + (size_t)blockIdx.x * S1;

    float dreg[32];
    #pragma unroll
    for (int c = 0; c < 8; c++) {
        float w[24];
        int base = 1024 * c + 4 * tid;          // < 8192 always
        int lo = 2 * base - 16;                 // 16B aligned; lo+24 <= 16384
        if (lo >= 0) {
            const float4* p = reinterpret_cast<const float4*>(xin + lo);
            #pragma unroll
            for (int j = 0; j < 6; j++) {
                float4 v = p[j];
                w[4*j] = v.x; w[4*j+1] = v.y; w[4*j+2] = v.z; w[4*j+3] = v.w;
            }
        } else {                                 // only c==0, tid<2
            #pragma unroll
            for (int j = 0; j < 24; j++) {
                int m = lo + j;
                m = (m < 0) ? (-1 - m) : m;
                w[j] = xin[m];
            }
        }
        float o[8];
        #pragma unroll
        for (int r = 0; r < 4; r++) {
            float a = 0.f, d = 0.f;
            #pragma unroll
            for (int t = 0; t < 16; t++) {
                float xv = w[2 * r + t + 2];
                a = fmaf(H[t], xv, a);
                d = fmaf((t & 1) ? -H[15 - t] : H[15 - t], xv, d);
            }
            o[2*r] = a; o[2*r+1] = d;
            dreg[4 * c + r] = d;
        }
        *reinterpret_cast<float4*>(pa + base) = make_float4(o[0], o[2], o[4], o[6]);
        *reinterpret_cast<float4*>(pd + base) = make_float4(o[1], o[3], o[5], o[7]);
    }
    if (tid == 255) {                            // tail k = 8192..8198
        for (int e = 0; e < 7; e++) {
            int k = 8192 + e;
            float a = 0.f, d = 0.f;
            #pragma unroll
            for (int t = 0; t < 16; t++) {
                int m = 2 * k + t - 14;
                if (m >= LROW) m = 2 * LROW - 1 - m;
                float xv = xin[m];
                a = fmaf(H[t], xv, a);
                d = fmaf((t & 1) ? -H[15 - t] : H[15 - t], xv, d);
            }
            pa[k] = a; pd[k] = d; s_tail[e] = d;
        }
    }
    if (tid == 0) { s_pref = 0u; s_rank = (N1 - 1) / 2; }
    __syncthreads();

    // exact median of |d1| via 4-round radix select on fp32 bits
    for (int b = 3; b >= 0; --b) {
        s_hist[tid] = 0;
        __syncthreads();
        const unsigned pref = s_pref;
        const int rank = s_rank;
        const int sh = b * 8;
        #pragma unroll
        for (int j = 0; j < 32; j++) {
            unsigned u = __float_as_uint(fabsf(dreg[j]));
            bool mt = (b == 3) || ((u >> (sh + 8)) == pref);
            unsigned bin = (u >> sh) & 255u;
            unsigned key = mt ? bin : 256u;
            unsigned grp = __match_any_sync(0xffffffffu, key);
            int leader = __ffs(grp) - 1;
            if (mt && lane == leader)
                atomicAdd(&s_hist[bin], __popc(grp));
        }
        if (tid == 0) {
            for (int e = 0; e < 7; e++) {
                unsigned u = __float_as_uint(fabsf(s_tail[e]));
                bool mt = (b == 3) || ((u >> (sh + 8)) == pref);
                if (mt) atomicAdd(&s_hist[(u >> sh) & 255u], 1);
            }
        }
        __syncthreads();
        int v = s_hist[tid];
        int incl = v;
        #pragma unroll
        for (int o = 1; o < 32; o <<= 1) {
            int tsh = __shfl_up_sync(0xffffffffu, incl, o);
            if (lane >= o) incl += tsh;
        }
        if (lane == 31) s_wsum[warp] = incl;
        __syncthreads();
        if (tid == 0) {
            int acc = 0;
            #pragma unroll
            for (int wq = 0; wq < 8; wq++) { s_woff[wq] = acc; acc += s_wsum[wq]; }
        }
        __syncthreads();
        int excl = incl - v + s_woff[warp];
        if (rank >= excl && rank < excl + v) {
            s_pref = (pref << 8) | (unsigned)tid;
            s_rank = rank - excl;
        }
        __syncthreads();
    }
    if (tid == 0) {
        float med = __uint_as_float(s_pref);
        thr_out[blockIdx.x] = (med / 0.6745f) * 4.4054649f;  // * sqrt(2 ln 16384)
    }
}

// ===================== streaming DWT level (grid: x=positions/1024, y=rows) ====
__global__ void __launch_bounds__(256)
k_dwt(const float* __restrict__ in, float* __restrict__ oa, float* __restrict__ od,
      int n, int nout, int sin, int sout)
{
    const float H[16] = HLIT;
    int base = 4 * (blockIdx.x * 256 + threadIdx.x);
    if (base >= nout) return;
    const float* xin = in + (size_t)blockIdx.y * sin;
    float* pa = oa + (size_t)blockIdx.y * sout;
    float* pd = od + (size_t)blockIdx.y * sout;

    float w[24];
    int lo = 2 * base - 16;                      // 16B aligned
    if (lo >= 0 && lo + 24 <= n) {
        const float4* p = reinterpret_cast<const float4*>(xin + lo);
        #pragma unroll
        for (int j = 0; j < 6; j++) {
            float4 v = p[j];
            w[4*j] = v.x; w[4*j+1] = v.y; w[4*j+2] = v.z; w[4*j+3] = v.w;
        }
    } else {
        #pragma unroll
        for (int j = 0; j < 24; j++) {
            int m = lo + j;
            m = (m < 0) ? (-1 - m) : m;
            m = (m >= n) ? (2 * n - 1 - m) : m;
            w[j] = xin[m];
        }
    }
    float o[8];
    #pragma unroll
    for (int r = 0; r < 4; r++) {
        float a = 0.f, d = 0.f;
        #pragma unroll
        for (int t = 0; t < 16; t++) {
            float xv = w[2 * r + t + 2];
            a = fmaf(H[t], xv, a);
            d = fmaf((t & 1) ? -H[15 - t] : H[15 - t], xv, d);
        }
        o[2*r] = a; o[2*r+1] = d;
    }
    if (base + 4 <= nout) {
        *reinterpret_cast<float4*>(pa + base) = make_float4(o[0], o[2], o[4], o[6]);
        *reinterpret_cast<float4*>(pd + base) = make_float4(o[1], o[3], o[5], o[7]);
    } else {
        #pragma unroll
        for (int r = 0; r < 4; r++)
            if (base + r < nout) { pa[base + r] = o[2*r]; pd[base + r] = o[2*r+1]; }
    }
}

// ===================== streaming IDWT level with fused soft threshold ==========
// rec[2p]   = sum_s H[14-2s]*ca[p+s] + H[2s+1]*st(cd[p+s])
// rec[2p+1] = sum_s H[15-2s]*ca[p+s] - H[2s]  *st(cd[p+s]),  p in [0, n-8]
__global__ void __launch_bounds__(256)
k_idwt(const float* __restrict__ ca, const float* __restrict__ cd,
       const float* __restrict__ thr_arr, float* __restrict__ rec,
       int n, int sca, int scd, int srec)
{
    const float H[16] = HLIT;
    int p0 = 4 * (blockIdx.x * 256 + threadIdx.x);
    int plim = n - 7;
    if (p0 >= plim) return;
    const float thr = __ldg(thr_arr + blockIdx.y);
    const float* pa = ca + (size_t)blockIdx.y * sca;
    const float* pd = cd + (size_t)blockIdx.y * scd;
    float* pr = rec + (size_t)blockIdx.y * srec;

    float a[12], d[12];
    if (p0 + 12 <= n) {
        const float4* qa = reinterpret_cast<const float4*>(pa + p0);
        const float4* qd = reinterpret_cast<const float4*>(pd + p0);
        #pragma unroll
        for (int j = 0; j < 3; j++) {
            float4 va = qa[j], vd = qd[j];
            a[4*j] = va.x; a[4*j+1] = va.y; a[4*j+2] = va.z; a[4*j+3] = va.w;
            d[4*j] = vd.x; d[4*j+1] = vd.y; d[4*j+2] = vd.z; d[4*j+3] = vd.w;
        }
    } else {
        #pragma unroll
        for (int j = 0; j < 12; j++) {
            int q = p0 + j; if (q > n - 1) q = n - 1;
            a[j] = pa[q]; d[j] = pd[q];
        }
    }
    #pragma unroll
    for (int j = 0; j < 12; j++) d[j] = softthr(d[j], thr);

    float o[8];
    #pragma unroll
    for (int pp = 0; pp < 4; pp++) {
        float e = 0.f, od = 0.f;
        #pragma unroll
        for (int s = 0; s < 8; s++) {
            e  = fmaf(H[14 - 2 * s], a[pp + s], e);
            e  = fmaf(H[2 * s + 1],  d[pp + s], e);
            od = fmaf(H[15 - 2 * s], a[pp + s], od);
            od = fmaf(-H[2 * s],     d[pp + s], od);
        }
        o[2*pp] = e; o[2*pp+1] = od;
    }
    if (p0 + 4 <= plim) {
        float4* q = reinterpret_cast<float4*>(pr + 2 * p0);
        q[0] = make_float4(o[0], o[1], o[2], o[3]);
        q[1] = make_float4(o[4], o[5], o[6], o[7]);
    } else {
        #pragma unroll
        for (int pp = 0; pp < 4; pp++) {
            if (p0 + pp < plim) {
                pr[2 * (p0 + pp)]     = o[2*pp];
                pr[2 * (p0 + pp) + 1] = o[2*pp+1];
            }
        }
    }
}

static inline int gx_for(int work) { return (work + 1023) / 1024; }  // 4 per thread, 256 thr

extern "C" void kernel_launch(void* const* d_in, const int* in_sizes, int n_in,
                              void* d_out, int out_size)
{
    const float* x = (const float*)d_in[0];
    float* out = (float*)d_out;
    int rows = in_sizes[0] / LROW;   // 2048

    float *a1, *d1, *a2, *d2, *a3, *d3, *a4, *d4, *thr;
    cudaGetSymbolAddress((void**)&a1, g_a1);
    cudaGetSymbolAddress((void**)&d1, g_d1);
    cudaGetSymbolAddress((void**)&a2, g_a2);
    cudaGetSymbolAddress((void**)&d2, g_d2);
    cudaGetSymbolAddress((void**)&a3, g_a3);
    cudaGetSymbolAddress((void**)&d3, g_d3);
    cudaGetSymbolAddress((void**)&a4, g_a4);
    cudaGetSymbolAddress((void**)&d4, g_d4);
    cudaGetSymbolAddress((void**)&thr, g_thr);

    // analysis
    k_dwt1_med<<<rows, 256>>>(x, a1, d1, thr);
    k_dwt<<<dim3(gx_for(N2), rows), 256>>>(a1, a2, d2, N1, N2, S1, S2);
    k_dwt<<<dim3(gx_for(N3), rows), 256>>>(a2, a3, d3, N2, N3, S2, S3);
    k_dwt<<<dim3(gx_for(N4), rows), 256>>>(a3, a4, d4, N3, N4, S3, S4);

    // synthesis (rec buffers overlay dead a-buffers)
    float* rec4 = a3;   // a3 dead after level-4 DWT
    float* rec3 = a2;   // a2 dead after level-3 DWT
    float* rec2 = a1;   // a1 dead after level-2 DWT
    k_idwt<<<dim3(gx_for(N4 - 7), rows), 256>>>(a4,   d4, thr, rec4, N4, S4, S4, S3);
    k_idwt<<<dim3(gx_for(N3 - 7), rows), 256>>>(rec4, d3, thr, rec3, N3, S3, S3, S2);
    k_idwt<<<dim3(gx_for(N2 - 7), rows), 256>>>(rec3, d2, thr, rec2, N2, S2, S2, S1);
    k_idwt<<<dim3(gx_for(N1 - 7), rows), 256>>>(rec2, d1, thr, out,  N1, S1, S1, LROW);
}

// round 5
// speedup vs baseline: 1.2525x; 1.0426x over previous
#include <cuda_runtime.h>

#define LROW 16384
#define N1 8199
#define N2 4107
#define N3 2061
#define N4 1038
#define ROWS_MAX 2048

// padded row strides (multiples of 8 floats -> 32B alignment preserved per row)
#define S1 8200
#define S2 4112
#define S3 2064
#define S4 1040

// skewed smem addressing: conflict-free for strides 1,2,4,8
#define SK(i) ((i) + ((i) >> 5))
#define A2_SK 4236   // flat 4108
#define A3_SK 2126   // flat 2062

__device__ float g_a1[(size_t)ROWS_MAX * S1];   // a1, later rec2
__device__ float g_d1[(size_t)ROWS_MAX * S1];
__device__ float g_d2[(size_t)ROWS_MAX * S2];
__device__ float g_d3[(size_t)ROWS_MAX * S3];
__device__ float g_d4[(size_t)ROWS_MAX * S4];
__device__ float g_a4[(size_t)ROWS_MAX * S4];
__device__ float g_thr[ROWS_MAX];

#define HLIT { \
    0.05441584224308161f,    0.3128715909144659f,    0.6756307362980128f, \
    0.5853546836548691f,    -0.015829105256023893f, -0.2840155429624281f, \
    0.00047248457399797254f, 0.128747426620186f,    -0.01736930100202211f, \
   -0.04408825393106472f,    0.013981027917015516f,  0.008746094047015655f, \
   -0.00487035299301066f,   -0.0003917403729959771f, 0.0006754494059985568f, \
   -0.00011747678400228192f }

__device__ __forceinline__ float softthr(float v, float thr) {
    float av = fabsf(v) - thr;
    return av > 0.f ? copysignf(av, v) : 0.f;
}

// ---------- core conv helpers ----------
__device__ __forceinline__ void dwt4(const float* w, float* o) {
    const float H[16] = HLIT;
    #pragma unroll
    for (int r = 0; r < 4; r++) {
        float a = 0.f, d = 0.f;
        #pragma unroll
        for (int t = 0; t < 16; t++) {
            float xv = w[2 * r + t];
            a = fmaf(H[t], xv, a);
            d = fmaf((t & 1) ? -H[15 - t] : H[15 - t], xv, d);
        }
        o[2 * r] = a; o[2 * r + 1] = d;
    }
}

// ===================== K1: streaming level-1 DWT ==============================
__global__ void __launch_bounds__(256)
k_dwt1(const float* __restrict__ x, float* __restrict__ oa, float* __restrict__ od)
{
    int base = 4 * (blockIdx.x * 256 + threadIdx.x);
    if (base >= N1) return;
    const float* xin = x + (size_t)blockIdx.y * LROW;
    float* pa = oa + (size_t)blockIdx.y * S1;
    float* pd = od + (size_t)blockIdx.y * S1;

    float w[24];
    int lo = 2 * base - 16;
    if (lo >= 0 && lo + 24 <= LROW) {
        const float4* p = reinterpret_cast<const float4*>(xin + lo);
        #pragma unroll
        for (int j = 0; j < 6; j++) {
            float4 v = p[j];
            w[4*j] = v.x; w[4*j+1] = v.y; w[4*j+2] = v.z; w[4*j+3] = v.w;
        }
    } else {
        #pragma unroll
        for (int j = 0; j < 24; j++) {
            int m = lo + j;
            m = (m < 0) ? (-1 - m) : m;
            m = (m >= LROW) ? (2 * LROW - 1 - m) : m;
            w[j] = xin[m];
        }
    }
    float o[8];
    dwt4(w + 2, o);
    if (base + 4 <= N1) {
        *reinterpret_cast<float4*>(pa + base) = make_float4(o[0], o[2], o[4], o[6]);
        *reinterpret_cast<float4*>(pd + base) = make_float4(o[1], o[3], o[5], o[7]);
    } else {
        #pragma unroll
        for (int r = 0; r < 4; r++)
            if (base + r < N1) { pa[base + r] = o[2*r]; pd[base + r] = o[2*r+1]; }
    }
}

// ===================== K2: per-row exact median of |d1| -> thr ================
__global__ void __launch_bounds__(256)
k_med(const float* __restrict__ d1, float* __restrict__ thr_out)
{
    __shared__ int      s_hist[256];
    __shared__ int      s_wsum[8];
    __shared__ int      s_woff[8];
    __shared__ unsigned s_pref;
    __shared__ int      s_rank;

    const int tid = threadIdx.x, lane = tid & 31, warp = tid >> 5;
    const float* pd = d1 + (size_t)blockIdx.x * S1;

    float dreg[32];
    #pragma unroll
    for (int c = 0; c < 8; c++) {
        float4 v = *reinterpret_cast<const float4*>(pd + 1024 * c + 4 * tid);
        dreg[4*c] = v.x; dreg[4*c+1] = v.y; dreg[4*c+2] = v.z; dreg[4*c+3] = v.w;
    }
    float dtail = (tid < 7) ? pd[8192 + tid] : 0.f;

    if (tid == 0) { s_pref = 0u; s_rank = (N1 - 1) / 2; }
    __syncthreads();

    for (int b = 3; b >= 0; --b) {
        s_hist[tid] = 0;
        __syncthreads();
        const unsigned pref = s_pref;
        const int rank = s_rank;
        const int sh = b * 8;
        #pragma unroll
        for (int j = 0; j < 32; j++) {
            unsigned u = __float_as_uint(fabsf(dreg[j]));
            bool mt = (b == 3) || ((u >> (sh + 8)) == pref);
            unsigned bin = (u >> sh) & 255u;
            unsigned key = mt ? bin : 256u;
            unsigned grp = __match_any_sync(0xffffffffu, key);
            int leader = __ffs(grp) - 1;
            if (mt && lane == leader)
                atomicAdd(&s_hist[bin], __popc(grp));
        }
        if (tid < 7) {
            unsigned u = __float_as_uint(fabsf(dtail));
            bool mt = (b == 3) || ((u >> (sh + 8)) == pref);
            if (mt) atomicAdd(&s_hist[(u >> sh) & 255u], 1);
        }
        __syncthreads();
        int v = s_hist[tid];
        int incl = v;
        #pragma unroll
        for (int o = 1; o < 32; o <<= 1) {
            int tsh = __shfl_up_sync(0xffffffffu, incl, o);
            if (lane >= o) incl += tsh;
        }
        if (lane == 31) s_wsum[warp] = incl;
        __syncthreads();
        if (tid == 0) {
            int acc = 0;
            #pragma unroll
            for (int wq = 0; wq < 8; wq++) { s_woff[wq] = acc; acc += s_wsum[wq]; }
        }
        __syncthreads();
        int excl = incl - v + s_woff[warp];
        if (rank >= excl && rank < excl + v) {
            s_pref = (pref << 8) | (unsigned)tid;
            s_rank = rank - excl;
        }
        __syncthreads();
    }
    if (tid == 0) {
        float med = __uint_as_float(s_pref);
        thr_out[blockIdx.x] = (med / 0.6745f) * 4.4054649f;  // * sqrt(2 ln 16384)
    }
}

// ===================== K3: fused DWT levels 2-4 (block per row) ===============
__global__ void __launch_bounds__(256)
k_dwt234(const float* __restrict__ a1, float* __restrict__ d2g,
         float* __restrict__ d3g, float* __restrict__ d4g, float* __restrict__ a4g)
{
    __shared__ float A2[A2_SK];
    __shared__ float A3[A3_SK];

    const int tid = threadIdx.x;
    const int row = blockIdx.x;
    const float* pin = a1  + (size_t)row * S1;
    float* pd2 = d2g + (size_t)row * S2;
    float* pd3 = d3g + (size_t)row * S3;
    float* pd4 = d4g + (size_t)row * S4;
    float* pa4 = a4g + (size_t)row * S4;

    // ---- level 2: global a1 -> A2 smem + d2 global ----
    for (int base = 4 * tid; base < N2; base += 1024) {
        float w[24];
        int lo = 2 * base - 16;
        if (lo >= 0 && lo + 24 <= N1) {
            const float4* p = reinterpret_cast<const float4*>(pin + lo);
            #pragma unroll
            for (int j = 0; j < 6; j++) {
                float4 v = p[j];
                w[4*j] = v.x; w[4*j+1] = v.y; w[4*j+2] = v.z; w[4*j+3] = v.w;
            }
        } else {
            #pragma unroll
            for (int j = 0; j < 24; j++) {
                int m = lo + j;
                m = (m < 0) ? (-1 - m) : m;
                m = (m >= N1) ? (2 * N1 - 1 - m) : m;
                w[j] = pin[m];
            }
        }
        float o[8];
        dwt4(w + 2, o);
        if (base + 4 <= N2) {
            #pragma unroll
            for (int r = 0; r < 4; r++) A2[SK(base + r)] = o[2*r];
            *reinterpret_cast<float4*>(pd2 + base) = make_float4(o[1], o[3], o[5], o[7]);
        } else {
            #pragma unroll
            for (int r = 0; r < 4; r++)
                if (base + r < N2) { A2[SK(base + r)] = o[2*r]; pd2[base + r] = o[2*r+1]; }
        }
    }
    __syncthreads();

    // ---- level 3: A2 smem -> A3 smem + d3 global ----
    for (int base = 4 * tid; base < N3; base += 1024) {
        float w[22];
        int m0 = 2 * base - 14;
        #pragma unroll
        for (int j = 0; j < 22; j++) {
            int m = m0 + j;
            m = (m < 0) ? (-1 - m) : m;
            m = (m >= N2) ? (2 * N2 - 1 - m) : m;
            w[j] = A2[SK(m)];
        }
        float o[8];
        dwt4(w, o);
        if (base + 4 <= N3) {
            #pragma unroll
            for (int r = 0; r < 4; r++) A3[SK(base + r)] = o[2*r];
            *reinterpret_cast<float4*>(pd3 + base) = make_float4(o[1], o[3], o[5], o[7]);
        } else {
            #pragma unroll
            for (int r = 0; r < 4; r++)
                if (base + r < N3) { A3[SK(base + r)] = o[2*r]; pd3[base + r] = o[2*r+1]; }
        }
    }
    __syncthreads();

    // ---- level 4: A3 smem -> a4/d4 global ----
    for (int base = 4 * tid; base < N4; base += 1024) {
        float w[22];
        int m0 = 2 * base - 14;
        #pragma unroll
        for (int j = 0; j < 22; j++) {
            int m = m0 + j;
            m = (m < 0) ? (-1 - m) : m;
            m = (m >= N3) ? (2 * N3 - 1 - m) : m;
            w[j] = A3[SK(m)];
        }
        float o[8];
        dwt4(w, o);
        if (base + 4 <= N4) {
            *reinterpret_cast<float4*>(pa4 + base) = make_float4(o[0], o[2], o[4], o[6]);
            *reinterpret_cast<float4*>(pd4 + base) = make_float4(o[1], o[3], o[5], o[7]);
        } else {
            #pragma unroll
            for (int r = 0; r < 4; r++)
                if (base + r < N4) { pa4[base + r] = o[2*r]; pd4[base + r] = o[2*r+1]; }
        }
    }
}

// ---------- idwt core: 4 pairs from a[12], d[12] ----------
__device__ __forceinline__ void idwt4(const float* a, const float* d, float* o) {
    const float H[16] = HLIT;
    #pragma unroll
    for (int pp = 0; pp < 4; pp++) {
        float e = 0.f, od = 0.f;
        #pragma unroll
        for (int s = 0; s < 8; s++) {
            e  = fmaf(H[14 - 2 * s], a[pp + s], e);
            e  = fmaf(H[2 * s + 1],  d[pp + s], e);
            od = fmaf(H[15 - 2 * s], a[pp + s], od);
            od = fmaf(-H[2 * s],     d[pp + s], od);
        }
        o[2*pp] = e; o[2*pp+1] = od;
    }
}

// ===================== K4: fused IDWT 4->3->2 (block per row) =================
__global__ void __launch_bounds__(256)
k_idwt432(const float* __restrict__ a4g, const float* __restrict__ d4g,
          const float* __restrict__ d3g, const float* __restrict__ d2g,
          const float* __restrict__ thr_arr, float* __restrict__ rec2g)
{
    __shared__ float R4[A3_SK];   // flat 2062
    __shared__ float R3[A2_SK];   // flat 4108

    const int tid = threadIdx.x;
    const int row = blockIdx.x;
    const float thr = __ldg(thr_arr + row);
    const float* pa4 = a4g + (size_t)row * S4;
    const float* pd4 = d4g + (size_t)row * S4;
    const float* pd3 = d3g + (size_t)row * S3;
    const float* pd2 = d2g + (size_t)row * S2;
    float* prec2 = rec2g + (size_t)row * S1;

    // ---- level 4 IDWT: global a4,d4 -> R4 smem ----
    {
        int plim = N4 - 7;
        for (int p0 = 4 * tid; p0 < plim; p0 += 1024) {
            float a[12], d[12];
            if (p0 + 12 <= N4) {
                const float4* qa = reinterpret_cast<const float4*>(pa4 + p0);
                const float4* qd = reinterpret_cast<const float4*>(pd4 + p0);
                #pragma unroll
                for (int j = 0; j < 3; j++) {
                    float4 va = qa[j], vd = qd[j];
                    a[4*j] = va.x; a[4*j+1] = va.y; a[4*j+2] = va.z; a[4*j+3] = va.w;
                    d[4*j] = vd.x; d[4*j+1] = vd.y; d[4*j+2] = vd.z; d[4*j+3] = vd.w;
                }
            } else {
                #pragma unroll
                for (int j = 0; j < 12; j++) {
                    int q = p0 + j; if (q > N4 - 1) q = N4 - 1;
                    a[j] = pa4[q]; d[j] = pd4[q];
                }
            }
            #pragma unroll
            for (int j = 0; j < 12; j++) d[j] = softthr(d[j], thr);
            float o[8];
            idwt4(a, d, o);
            #pragma unroll
            for (int pp = 0; pp < 4; pp++) {
                if (p0 + pp < plim) {
                    R4[SK(2 * (p0 + pp))]     = o[2*pp];
                    R4[SK(2 * (p0 + pp) + 1)] = o[2*pp+1];
                }
            }
        }
    }
    __syncthreads();

    // ---- level 3 IDWT: R4 smem (ca) + global d3 -> R3 smem ----
    {
        int plim = N3 - 7;
        for (int p0 = 4 * tid; p0 < plim; p0 += 1024) {
            float a[12], d[12];
            #pragma unroll
            for (int j = 0; j < 12; j++) {
                int q = p0 + j; if (q > N3 - 1) q = N3 - 1;
                a[j] = R4[SK(q)];
            }
            if (p0 + 12 <= N3) {
                const float4* qd = reinterpret_cast<const float4*>(pd3 + p0);
                #pragma unroll
                for (int j = 0; j < 3; j++) {
                    float4 vd = qd[j];
                    d[4*j] = vd.x; d[4*j+1] = vd.y; d[4*j+2] = vd.z; d[4*j+3] = vd.w;
                }
            } else {
                #pragma unroll
                for (int j = 0; j < 12; j++) {
                    int q = p0 + j; if (q > N3 - 1) q = N3 - 1;
                    d[j] = pd3[q];
                }
            }
            #pragma unroll
            for (int j = 0; j < 12; j++) d[j] = softthr(d[j], thr);
            float o[8];
            idwt4(a, d, o);
            #pragma unroll
            for (int pp = 0; pp < 4; pp++) {
                if (p0 + pp < plim) {
                    R3[SK(2 * (p0 + pp))]     = o[2*pp];
                    R3[SK(2 * (p0 + pp) + 1)] = o[2*pp+1];
                }
            }
        }
    }
    __syncthreads();

    // ---- level 2 IDWT: R3 smem (ca) + global d2 -> rec2 global ----
    {
        int plim = N2 - 7;
        for (int p0 = 4 * tid; p0 < plim; p0 += 1024) {
            float a[12], d[12];
            #pragma unroll
            for (int j = 0; j < 12; j++) {
                int q = p0 + j; if (q > N2 - 1) q = N2 - 1;
                a[j] = R3[SK(q)];
            }
            if (p0 + 12 <= N2) {
                const float4* qd = reinterpret_cast<const float4*>(pd2 + p0);
                #pragma unroll
                for (int j = 0; j < 3; j++) {
                    float4 vd = qd[j];
                    d[4*j] = vd.x; d[4*j+1] = vd.y; d[4*j+2] = vd.z; d[4*j+3] = vd.w;
                }
            } else {
                #pragma unroll
                for (int j = 0; j < 12; j++) {
                    int q = p0 + j; if (q > N2 - 1) q = N2 - 1;
                    d[j] = pd2[q];
                }
            }
            #pragma unroll
            for (int j = 0; j < 12; j++) d[j] = softthr(d[j], thr);
            float o[8];
            idwt4(a, d, o);
            if (p0 + 4 <= plim) {
                float4* q = reinterpret_cast<float4*>(prec2 + 2 * p0);
                q[0] = make_float4(o[0], o[1], o[2], o[3]);
                q[1] = make_float4(o[4], o[5], o[6], o[7]);
            } else {
                #pragma unroll
                for (int pp = 0; pp < 4; pp++) {
                    if (p0 + pp < plim) {
                        prec2[2 * (p0 + pp)]     = o[2*pp];
                        prec2[2 * (p0 + pp) + 1] = o[2*pp+1];
                    }
                }
            }
        }
    }
}

// ===================== K5: streaming final IDWT ===============================
__global__ void __launch_bounds__(256)
k_idwt1(const float* __restrict__ ca, const float* __restrict__ cd,
        const float* __restrict__ thr_arr, float* __restrict__ rec)
{
    int p0 = 4 * (blockIdx.x * 256 + threadIdx.x);
    int plim = N1 - 7;
    if (p0 >= plim) return;
    const float thr = __ldg(thr_arr + blockIdx.y);
    const float* pa = ca + (size_t)blockIdx.y * S1;
    const float* pd = cd + (size_t)blockIdx.y * S1;
    float* pr = rec + (size_t)blockIdx.y * LROW;

    float a[12], d[12];
    if (p0 + 12 <= N1) {
        const float4* qa = reinterpret_cast<const float4*>(pa + p0);
        const float4* qd = reinterpret_cast<const float4*>(pd + p0);
        #pragma unroll
        for (int j = 0; j < 3; j++) {
            float4 va = qa[j], vd = qd[j];
            a[4*j] = va.x; a[4*j+1] = va.y; a[4*j+2] = va.z; a[4*j+3] = va.w;
            d[4*j] = vd.x; d[4*j+1] = vd.y; d[4*j+2] = vd.z; d[4*j+3] = vd.w;
        }
    } else {
        #pragma unroll
        for (int j = 0; j < 12; j++) {
            int q = p0 + j; if (q > N1 - 1) q = N1 - 1;
            a[j] = pa[q]; d[j] = pd[q];
        }
    }
    #pragma unroll
    for (int j = 0; j < 12; j++) d[j] = softthr(d[j], thr);

    float o[8];
    idwt4(a, d, o);
    if (p0 + 4 <= plim) {
        float4* q = reinterpret_cast<float4*>(pr + 2 * p0);
        q[0] = make_float4(o[0], o[1], o[2], o[3]);
        q[1] = make_float4(o[4], o[5], o[6], o[7]);
    } else {
        #pragma unroll
        for (int pp = 0; pp < 4; pp++) {
            if (p0 + pp < plim) {
                pr[2 * (p0 + pp)]     = o[2*pp];
                pr[2 * (p0 + pp) + 1] = o[2*pp+1];
            }
        }
    }
}

extern "C" void kernel_launch(void* const* d_in, const int* in_sizes, int n_in,
                              void* d_out, int out_size)
{
    const float* x = (const float*)d_in[0];
    float* out = (float*)d_out;
    int rows = in_sizes[0] / LROW;   // 2048

    float *a1, *d1, *d2, *d3, *d4, *a4, *thr;
    cudaGetSymbolAddress((void**)&a1, g_a1);
    cudaGetSymbolAddress((void**)&d1, g_d1);
    cudaGetSymbolAddress((void**)&d2, g_d2);
    cudaGetSymbolAddress((void**)&d3, g_d3);
    cudaGetSymbolAddress((void**)&d4, g_d4);
    cudaGetSymbolAddress((void**)&a4, g_a4);
    cudaGetSymbolAddress((void**)&thr, g_thr);

    int gx1 = (N1 + 1023) / 1024;    // 4 outputs per thread, 256 threads

    k_dwt1  <<<dim3(gx1, rows), 256>>>(x, a1, d1);
    k_med   <<<rows, 256>>>(d1, thr);
    k_dwt234<<<rows, 256>>>(a1, d2, d3, d4, a4);

    float* rec2 = a1;   // a1 dead after k_dwt234
    k_idwt432<<<rows, 256>>>(a4, d4, d3, d2, thr, rec2);
    k_idwt1  <<<dim3(gx1, rows), 256>>>(rec2, d1, thr, out);
}

// round 6
// speedup vs baseline: 1.3629x; 1.0881x over previous
#include <cuda_runtime.h>

#define LROW 16384
#define N1 8199
#define N2 4107
#define N3 2061
#define N4 1038
#define ROWS_MAX 2048

// global scratch row strides (floats, 16B-multiple)
#define S1 8200
#define S2 4112
#define S3 2064
#define S4 1040

__device__ float g_d1[(size_t)ROWS_MAX * S1];
__device__ float g_d2[(size_t)ROWS_MAX * S2];
__device__ float g_d3[(size_t)ROWS_MAX * S3];
__device__ float g_d4[(size_t)ROWS_MAX * S4];
__device__ float g_a4[(size_t)ROWS_MAX * S4];
__device__ float g_thr[ROWS_MAX];

// smem layouts (floats). fwd: A1[0,8208) A2[8208,12320), A3 overlays A1.
//                        inv: REC[0,8208) R3[8208,12320), R4 overlays REC.
#define SM_FLOATS 12320
#define SM_BYTES  (SM_FLOATS * 4)
#define OFF_HI    8208

#define HLIT { \
    0.05441584224308161f,    0.3128715909144659f,    0.6756307362980128f, \
    0.5853546836548691f,    -0.015829105256023893f, -0.2840155429624281f, \
    0.00047248457399797254f, 0.128747426620186f,    -0.01736930100202211f, \
   -0.04408825393106472f,    0.013981027917015516f,  0.008746094047015655f, \
   -0.00487035299301066f,   -0.0003917403729959771f, 0.0006754494059985568f, \
   -0.00011747678400228192f }

__device__ __forceinline__ float softthr(float v, float thr) {
    float av = fabsf(v) - thr;
    return av > 0.f ? copysignf(av, v) : 0.f;
}

__device__ __forceinline__ void dwt4(const float* w, float* o) {
    const float H[16] = HLIT;
    #pragma unroll
    for (int r = 0; r < 4; r++) {
        float a = 0.f, d = 0.f;
        #pragma unroll
        for (int t = 0; t < 16; t++) {
            float xv = w[2 * r + t];
            a = fmaf(H[t], xv, a);
            d = fmaf((t & 1) ? -H[15 - t] : H[15 - t], xv, d);
        }
        o[2 * r] = a; o[2 * r + 1] = d;
    }
}

__device__ __forceinline__ void idwt4(const float* a, const float* d, float* o) {
    const float H[16] = HLIT;
    #pragma unroll
    for (int pp = 0; pp < 4; pp++) {
        float e = 0.f, od = 0.f;
        #pragma unroll
        for (int s = 0; s < 8; s++) {
            e  = fmaf(H[14 - 2 * s], a[pp + s], e);
            e  = fmaf(H[2 * s + 1],  d[pp + s], e);
            od = fmaf(H[15 - 2 * s], a[pp + s], od);
            od = fmaf(-H[2 * s],     d[pp + s], od);
        }
        o[2*pp] = e; o[2*pp+1] = od;
    }
}

// generic DWT pass over smem input (vectorized fast path; reflect at edges)
__device__ __forceinline__ void dwt_pass(const float* __restrict__ xin, int n,
                                         float* __restrict__ ca_smem,
                                         float* __restrict__ cd_gmem, int nout,
                                         int tid)
{
    for (int base = 4 * tid; base < nout; base += 1024) {
        float w[24];
        int lo = 2 * base - 16;
        if (lo >= 0 && lo + 24 <= n) {
            #pragma unroll
            for (int j = 0; j < 6; j++) {
                float4 v = *reinterpret_cast<const float4*>(xin + lo + 4 * j);
                w[4*j] = v.x; w[4*j+1] = v.y; w[4*j+2] = v.z; w[4*j+3] = v.w;
            }
        } else {
            #pragma unroll
            for (int j = 0; j < 24; j++) {
                int m = lo + j;
                m = (m < 0) ? (-1 - m) : m;
                m = (m >= n) ? (2 * n - 1 - m) : m;
                w[j] = xin[m];
            }
        }
        float o[8];
        dwt4(w + 2, o);
        if (base + 4 <= nout) {
            *reinterpret_cast<float4*>(ca_smem + base) = make_float4(o[0], o[2], o[4], o[6]);
            *reinterpret_cast<float4*>(cd_gmem + base) = make_float4(o[1], o[3], o[5], o[7]);
        } else {
            #pragma unroll
            for (int r = 0; r < 4; r++)
                if (base + r < nout) { ca_smem[base + r] = o[2*r]; cd_gmem[base + r] = o[2*r+1]; }
        }
    }
}

// generic IDWT pass (vectorized fast path; clamp at right edge)
__device__ __forceinline__ void idwt_pass(const float* __restrict__ ca,
                                          const float* __restrict__ cd,
                                          int n, float thr,
                                          float* __restrict__ rec, int tid)
{
    int plim = n - 7;
    for (int p0 = 4 * tid; p0 < plim; p0 += 1024) {
        float a[12], d[12];
        if (p0 + 12 <= n) {
            #pragma unroll
            for (int j = 0; j < 3; j++) {
                float4 va = *reinterpret_cast<const float4*>(ca + p0 + 4 * j);
                float4 vd = *reinterpret_cast<const float4*>(cd + p0 + 4 * j);
                a[4*j] = va.x; a[4*j+1] = va.y; a[4*j+2] = va.z; a[4*j+3] = va.w;
                d[4*j] = vd.x; d[4*j+1] = vd.y; d[4*j+2] = vd.z; d[4*j+3] = vd.w;
            }
        } else {
            #pragma unroll
            for (int j = 0; j < 12; j++) {
                int q = p0 + j; if (q > n - 1) q = n - 1;
                a[j] = ca[q]; d[j] = cd[q];
            }
        }
        #pragma unroll
        for (int j = 0; j < 12; j++) d[j] = softthr(d[j], thr);
        float o[8];
        idwt4(a, d, o);
        if (p0 + 4 <= plim) {
            *reinterpret_cast<float4*>(rec + 2 * p0)     = make_float4(o[0], o[1], o[2], o[3]);
            *reinterpret_cast<float4*>(rec + 2 * p0 + 4) = make_float4(o[4], o[5], o[6], o[7]);
        } else {
            #pragma unroll
            for (int pp = 0; pp < 4; pp++)
                if (p0 + pp < plim) {
                    rec[2 * (p0 + pp)]     = o[2*pp];
                    rec[2 * (p0 + pp) + 1] = o[2*pp+1];
                }
        }
    }
}

// ============ K_fwd: level-1 DWT + exact median + DWT levels 2-4 ============
__global__ void __launch_bounds__(256, 3)
k_fwd(const float* __restrict__ x, float* __restrict__ d1g,
      float* __restrict__ d2g, float* __restrict__ d3g,
      float* __restrict__ d4g, float* __restrict__ a4g,
      float* __restrict__ thr_out)
{
    extern __shared__ float sm[];
    float* A1 = sm;              // flat 8200
    float* A2 = sm + OFF_HI;     // flat 4108
    float* A3 = sm;              // overlays dead A1

    __shared__ int      s_hist[256];
    __shared__ int      s_wsum[8];
    __shared__ int      s_woff[8];
    __shared__ unsigned s_pref;
    __shared__ int      s_rank;
    __shared__ float    s_tail[8];

    const int tid = threadIdx.x, lane = tid & 31, warp = tid >> 5;
    const int row = blockIdx.x;
    const float* xin = x + (size_t)row * LROW;
    float* pd1 = d1g + (size_t)row * S1;
    float* pd2 = d2g + (size_t)row * S2;
    float* pd3 = d3g + (size_t)row * S3;
    float* pd4 = d4g + (size_t)row * S4;
    float* pa4 = a4g + (size_t)row * S4;

    // ---- level 1: x -> A1 smem + d1 (regs + global) ----
    float dreg[32];
    #pragma unroll
    for (int c = 0; c < 8; c++) {
        int base = 1024 * c + 4 * tid;       // < 8192
        int lo = 2 * base - 16;              // lo+24 <= 16384 always
        float w[24];
        if (lo >= 0) {
            #pragma unroll
            for (int j = 0; j < 6; j++) {
                float4 v = *reinterpret_cast<const float4*>(xin + lo + 4 * j);
                w[4*j] = v.x; w[4*j+1] = v.y; w[4*j+2] = v.z; w[4*j+3] = v.w;
            }
        } else {                              // c==0, tid<2
            #pragma unroll
            for (int j = 0; j < 24; j++) {
                int m = lo + j;
                m = (m < 0) ? (-1 - m) : m;
                w[j] = xin[m];
            }
        }
        float o[8];
        dwt4(w + 2, o);
        *reinterpret_cast<float4*>(A1 + base)  = make_float4(o[0], o[2], o[4], o[6]);
        *reinterpret_cast<float4*>(pd1 + base) = make_float4(o[1], o[3], o[5], o[7]);
        dreg[4*c] = o[1]; dreg[4*c+1] = o[3]; dreg[4*c+2] = o[5]; dreg[4*c+3] = o[7];
    }
    if (tid == 255) {                         // tail k = 8192..8198
        const float H[16] = HLIT;
        for (int e = 0; e < 7; e++) {
            int k = 8192 + e;
            float a = 0.f, d = 0.f;
            #pragma unroll
            for (int t = 0; t < 16; t++) {
                int m = 2 * k + t - 14;
                if (m >= LROW) m = 2 * LROW - 1 - m;
                float xv = xin[m];
                a = fmaf(H[t], xv, a);
                d = fmaf((t & 1) ? -H[15 - t] : H[15 - t], xv, d);
            }
            A1[k] = a; pd1[k] = d; s_tail[e] = d;
        }
    }
    if (tid == 0) { s_pref = 0u; s_rank = (N1 - 1) / 2; }
    __syncthreads();

    // ---- exact median of |d1| (4-round radix select on fp32 bits) ----
    for (int b = 3; b >= 0; --b) {
        s_hist[tid] = 0;
        __syncthreads();
        const unsigned pref = s_pref;
        const int rank = s_rank;
        const int sh = b * 8;
        #pragma unroll
        for (int j = 0; j < 32; j++) {
            unsigned u = __float_as_uint(fabsf(dreg[j]));
            bool mt = (b == 3) || ((u >> (sh + 8)) == pref);
            unsigned bin = (u >> sh) & 255u;
            unsigned key = mt ? bin : 256u;
            unsigned grp = __match_any_sync(0xffffffffu, key);
            int leader = __ffs(grp) - 1;
            if (mt && lane == leader)
                atomicAdd(&s_hist[bin], __popc(grp));
        }
        if (tid == 0) {
            for (int e = 0; e < 7; e++) {
                unsigned u = __float_as_uint(fabsf(s_tail[e]));
                bool mt = (b == 3) || ((u >> (sh + 8)) == pref);
                if (mt) atomicAdd(&s_hist[(u >> sh) & 255u], 1);
            }
        }
        __syncthreads();
        int v = s_hist[tid];
        int incl = v;
        #pragma unroll
        for (int o = 1; o < 32; o <<= 1) {
            int tsh = __shfl_up_sync(0xffffffffu, incl, o);
            if (lane >= o) incl += tsh;
        }
        if (lane == 31) s_wsum[warp] = incl;
        __syncthreads();
        if (tid == 0) {
            int acc = 0;
            #pragma unroll
            for (int wq = 0; wq < 8; wq++) { s_woff[wq] = acc; acc += s_wsum[wq]; }
        }
        __syncthreads();
        int excl = incl - v + s_woff[warp];
        if (rank >= excl && rank < excl + v) {
            s_pref = (pref << 8) | (unsigned)tid;
            s_rank = rank - excl;
        }
        __syncthreads();
    }
    if (tid == 0) {
        float med = __uint_as_float(s_pref);
        thr_out[row] = (med / 0.6745f) * 4.4054649f;   // * sqrt(2 ln 16384)
    }
    // (last radix round ended with __syncthreads; A1 fully visible)

    // ---- levels 2-4 ----
    dwt_pass(A1, N1, A2, pd2, N2, tid);   __syncthreads();
    dwt_pass(A2, N2, A3, pd3, N3, tid);   __syncthreads();   // A3 overlays A1 (dead)
    // level 4: both outputs to global
    {
        for (int base = 4 * tid; base < N4; base += 1024) {
            float w[24];
            int lo = 2 * base - 16;
            if (lo >= 0 && lo + 24 <= N3) {
                #pragma unroll
                for (int j = 0; j < 6; j++) {
                    float4 v = *reinterpret_cast<const float4*>(A3 + lo + 4 * j);
                    w[4*j] = v.x; w[4*j+1] = v.y; w[4*j+2] = v.z; w[4*j+3] = v.w;
                }
            } else {
                #pragma unroll
                for (int j = 0; j < 24; j++) {
                    int m = lo + j;
                    m = (m < 0) ? (-1 - m) : m;
                    m = (m >= N3) ? (2 * N3 - 1 - m) : m;
                    w[j] = A3[m];
                }
            }
            float o[8];
            dwt4(w + 2, o);
            if (base + 4 <= N4) {
                *reinterpret_cast<float4*>(pa4 + base) = make_float4(o[0], o[2], o[4], o[6]);
                *reinterpret_cast<float4*>(pd4 + base) = make_float4(o[1], o[3], o[5], o[7]);
            } else {
                #pragma unroll
                for (int r = 0; r < 4; r++)
                    if (base + r < N4) { pa4[base + r] = o[2*r]; pd4[base + r] = o[2*r+1]; }
            }
        }
    }
}

// ============ K_inv: IDWT 4 -> 3 -> 2 -> 1, final level streams to out =======
__global__ void __launch_bounds__(256, 4)
k_inv(const float* __restrict__ a4g, const float* __restrict__ d4g,
      const float* __restrict__ d3g, const float* __restrict__ d2g,
      const float* __restrict__ d1g, const float* __restrict__ thr_arr,
      float* __restrict__ out)
{
    extern __shared__ float sm[];
    float* REC = sm;             // flat 8200
    float* R4  = sm;             // overlays REC (dead until level-2 writes)
    float* R3  = sm + OFF_HI;    // flat 4108

    const int tid = threadIdx.x;
    const int row = blockIdx.x;
    const float thr = __ldg(thr_arr + row);
    const float* pa4 = a4g + (size_t)row * S4;
    const float* pd4 = d4g + (size_t)row * S4;
    const float* pd3 = d3g + (size_t)row * S3;
    const float* pd2 = d2g + (size_t)row * S2;
    const float* pd1 = d1g + (size_t)row * S1;
    float* orow = out + (size_t)row * LROW;

    idwt_pass(pa4, pd4, N4, thr, R4, tid);   __syncthreads();  // R4 flat 2062
    idwt_pass(R4,  pd3, N3, thr, R3, tid);   __syncthreads();  // R3 flat 4108
    idwt_pass(R3,  pd2, N2, thr, REC, tid);  __syncthreads();  // REC flat 8200 (clobbers R4)
    idwt_pass(REC, pd1, N1, thr, orow, tid);                   // 16384 -> global
}

extern "C" void kernel_launch(void* const* d_in, const int* in_sizes, int n_in,
                              void* d_out, int out_size)
{
    const float* x = (const float*)d_in[0];
    float* out = (float*)d_out;
    int rows = in_sizes[0] / LROW;   // 2048

    float *d1, *d2, *d3, *d4, *a4, *thr;
    cudaGetSymbolAddress((void**)&d1, g_d1);
    cudaGetSymbolAddress((void**)&d2, g_d2);
    cudaGetSymbolAddress((void**)&d3, g_d3);
    cudaGetSymbolAddress((void**)&d4, g_d4);
    cudaGetSymbolAddress((void**)&a4, g_a4);
    cudaGetSymbolAddress((void**)&thr, g_thr);

    cudaFuncSetAttribute(k_fwd, cudaFuncAttributeMaxDynamicSharedMemorySize, SM_BYTES);
    cudaFuncSetAttribute(k_inv, cudaFuncAttributeMaxDynamicSharedMemorySize, SM_BYTES);

    k_fwd<<<rows, 256, SM_BYTES>>>(x, d1, d2, d3, d4, a4, thr);
    k_inv<<<rows, 256, SM_BYTES>>>(a4, d4, d3, d2, d1, thr, out);
}